// round 5
// baseline (speedup 1.0000x reference)
#include <cuda_runtime.h>
#include <cuda_bf16.h>

#define B_ 128
#define L_ 128
#define D_ 300
#define K_ 10
#define R_ 50
#define NAB (B_ * K_)   // 1280 ab problems

namespace {
constexpr int   NITER  = 20;
constexpr float EPS_   = 0.0025f;                  // 0.05^2
constexpr float IEPS   = 400.0f;                   // 1/EPS
constexpr float LOGR   = -3.9120230674743652f;     // -log(50)
constexpr float WR_    = 0.02f;                    // 1/50
constexpr float NEGV   = -1e9f;
constexpr float MARGIN = 10.0f;
constexpr float FLOOR_ = -3.0e38f;
}

// scratch (no allocations allowed)
__device__ float g_ab[NAB];
__device__ float g_tt[K_ * K_];

__device__ __forceinline__ float wred_max(float v) {
#pragma unroll
    for (int o = 16; o > 0; o >>= 1) v = fmaxf(v, __shfl_xor_sync(0xffffffffu, v, o));
    return v;
}
__device__ __forceinline__ float wred_sum(float v) {
#pragma unroll
    for (int o = 16; o > 0; o >>= 1) v += __shfl_xor_sync(0xffffffffu, v, o);
    return v;
}

// Log-domain Sinkhorn on a cost matrix in smem (row-major, stride CS; CS odd =>
// conflict-free row AND column access). loga: per-row log weights. logb is the
// uniform LOGR. nact = number of active rows (<= N). f,g potentials;
// fa = loga + f/eps, gb = LOGR + g/eps.
// gb is invariant across the whole f-phase and fa across the whole g-phase,
// so both are hoisted into registers outside the row/column loops.
template<int N, int M, int CS, int VN, int VM, int NW>
__device__ __forceinline__ void sinkhorn_run(
    const float* __restrict__ Cs, const float* __restrict__ loga,
    float* __restrict__ f, float* __restrict__ g,
    float* __restrict__ fa, float* __restrict__ gb,
    int tid, int nact)
{
    const int lane = tid & 31, warp = tid >> 5;
    for (int i = tid; i < M; i += NW * 32) { g[i] = 0.f; gb[i] = LOGR; }
    __syncthreads();

    for (int it = 0; it < NITER; ++it) {
        // ---- f-phase: f_n = -eps * LSE_m( gb_m - C_nm/eps ) ----
        float gbr[VM];
#pragma unroll
        for (int t = 0; t < VM; ++t) {
            int m = lane + 32 * t;
            gbr[t] = (m < M) ? gb[m] : FLOOR_;
        }
        for (int row = warp; row < nact; row += NW) {
            const float* Cr = Cs + row * CS;
            float v[VM];
            float mx = FLOOR_;
#pragma unroll
            for (int t = 0; t < VM; ++t) {
                int m = lane + 32 * t;
                if (m < M) { float x = fmaf(Cr[m], -IEPS, gbr[t]); v[t] = x; mx = fmaxf(mx, x); }
                else v[t] = FLOOR_;
            }
            mx = wred_max(mx);
            float s = 0.f;
#pragma unroll
            for (int t = 0; t < VM; ++t) {
                int m = lane + 32 * t;
                if (m < M) s += __expf(v[t] - mx);
            }
            s = wred_sum(s);
            if (lane == 0) {
                float fv = -EPS_ * (mx + __logf(s));
                f[row]  = fv;
                fa[row] = fmaf(fv, IEPS, loga[row]);
            }
        }
        __syncthreads();
        // ---- g-phase: g_m = -eps * LSE_n( fa_n - C_nm/eps ), rows >= nact excluded ----
        float far[VN];
#pragma unroll
        for (int t = 0; t < VN; ++t) {
            int n = lane + 32 * t;
            far[t] = (n < nact) ? fa[n] : FLOOR_;
        }
        for (int col = warp; col < M; col += NW) {
            float v[VN];
            float mx = FLOOR_;
#pragma unroll
            for (int t = 0; t < VN; ++t) {
                v[t] = FLOOR_;
                if (t * 32 < nact) {
                    int n = lane + 32 * t;
                    if (n < nact) { float x = fmaf(Cs[n * CS + col], -IEPS, far[t]); v[t] = x; mx = fmaxf(mx, x); }
                }
            }
            mx = wred_max(mx);
            float s = 0.f;
#pragma unroll
            for (int t = 0; t < VN; ++t) {
                if (t * 32 < nact) {
                    int n = lane + 32 * t;
                    if (n < nact) s += __expf(v[t] - mx);
                }
            }
            s = wred_sum(s);
            if (lane == 0) {
                float gv = -EPS_ * (mx + __logf(s));
                g[col]  = gv;
                gb[col] = fmaf(gv, IEPS, LOGR);
            }
        }
        __syncthreads();
    }
}

// ---------------------------------------------------------------------------
// Fused OT kernel. Blocks [0, 1280): ab problems ((b,k), NA x 50) — launched
// first, they are the long poles. Blocks [1280, 1380): tt problems (50x50).
// ---------------------------------------------------------------------------

// shared-memory carve (floats), ab path:
#define AB_AT   0        // At[16*132] transposed A chunk  (2112)
#define AB_TT   2112     // Tt[16*68]  transposed T chunk  (1088)
#define AB_CS   3200     // Cs[128*53]                     (6784)
#define AB_NA   9984     // na[128]
#define AB_NT   10112    // nt[64]
#define AB_LW   10176    // lw[128]
#define AB_WV   10304    // wv[128]
#define AB_F    10432    // f[128]
#define AB_FA   10560    // fa[128]
#define AB_G    10688    // g[64]
#define AB_GB   10752    // gb[64]
#define AB_RED  10816    // red[8]
#define SM_TOT  10824    // 43296 bytes

// tt path (aliases inside SM_TOT):
#define TT_AS   0        // As[64*17]  (1088)
#define TT_BS   1088     // Bs[64*17]  (1088)
#define TT_CS   2176     // Cs[50*51]  (2550)
#define TT_NA   4726     // na[64]
#define TT_NB   4790     // nb[64]
#define TT_LA   4854     // la[64]
#define TT_F    4918     // f[64]
#define TT_FA   4982     // fa[64]
#define TT_G    5046     // g[64]
#define TT_GB   5110     // gb[64]
#define TT_RED  5174     // red[8]

__global__ void __launch_bounds__(256, 3)
ot_kernel(const float* __restrict__ anchor, const float* __restrict__ weight,
          const float* __restrict__ t0, const int* __restrict__ len)
{
    __shared__ __align__(16) float sm[SM_TOT];
    const int tid  = threadIdx.x;
    const int lane = tid & 31, warp = tid >> 5;
    const int tx = tid & 15, ty = tid >> 4;

    if (blockIdx.x < NAB) {
        // ================= ab path: one CTA per (b,k) =================
        const int id = blockIdx.x;
        const int b  = id / K_;
        const int k  = id - b * K_;
        const float* A = anchor + b * (L_ * D_);
        const float* T = t0 + k * (R_ * D_);
        const int lenb = __ldg(len + b);
        const int NA   = min(L_, (lenb + 7) & ~7);   // active rows, multiple of 8

        float* At = sm + AB_AT;
        float* Tt = sm + AB_TT;
        float* Cs = sm + AB_CS;
        float* na = sm + AB_NA;
        float* nt = sm + AB_NT;
        float* lw = sm + AB_LW;
        float* wv = sm + AB_WV;

        // masked log-weights
        if (tid < L_) {
            float w = weight[b * L_ + tid];
            bool valid = tid < lenb;
            wv[tid] = valid ? w : 0.f;
            lw[tid] = valid ? __logf(fmaxf(w, 1e-12f)) : NEGV;
        }
        // squared norms (only active A rows needed)
        for (int row = warp; row < NA; row += 8) {
            float s = 0.f;
            for (int d = lane; d < D_; d += 32) { float x = A[row * D_ + d]; s = fmaf(x, x, s); }
            s = wred_sum(s);
            if (lane == 0) na[row] = s;
        }
        for (int row = warp; row < R_; row += 8) {
            float s = 0.f;
            for (int d = lane; d < D_; d += 32) { float x = T[row * D_ + d]; s = fmaf(x, x, s); }
            s = wred_sum(s);
            if (lane == 0) nt[row] = s;
        }
        __syncthreads();

        // GEMM: dot[l][r] for l < NA, r < 64 (cols >= 50 ignored).
        // 16x16 threads, 8x4 register tile, k-chunks of 16, transposed stages.
        float acc[8][4];
#pragma unroll
        for (int i = 0; i < 8; ++i)
#pragma unroll
            for (int j = 0; j < 4; ++j) acc[i][j] = 0.f;

        const bool rowAct = (ty * 8) < NA;
        for (int d0 = 0; d0 < D_; d0 += 16) {
            const int rem = D_ - d0;   // >=16 except last chunk (12)
            // stage A^T: At[kk*132 + l]
            for (int idx = tid; idx < NA * 16; idx += 256) {
                int kk = idx & 15, l = idx >> 4;
                At[kk * 132 + l] = (kk < rem) ? A[l * D_ + d0 + kk] : 0.f;
            }
            // stage T^T: Tt[kk*68 + r]
            for (int idx = tid; idx < 64 * 16; idx += 256) {
                int kk = idx & 15, r = idx >> 4;
                Tt[kk * 68 + r] = (r < R_ && kk < rem) ? T[r * D_ + d0 + kk] : 0.f;
            }
            __syncthreads();
            if (rowAct) {
#pragma unroll
                for (int kk = 0; kk < 16; ++kk) {
                    float4 a0 = *(const float4*)(At + kk * 132 + ty * 8);
                    float4 a1 = *(const float4*)(At + kk * 132 + ty * 8 + 4);
                    float4 t4 = *(const float4*)(Tt + kk * 68 + tx * 4);
                    float av[8] = {a0.x, a0.y, a0.z, a0.w, a1.x, a1.y, a1.z, a1.w};
                    float tv[4] = {t4.x, t4.y, t4.z, t4.w};
#pragma unroll
                    for (int i = 0; i < 8; ++i)
#pragma unroll
                        for (int j = 0; j < 4; ++j) acc[i][j] = fmaf(av[i], tv[j], acc[i][j]);
                }
            }
            __syncthreads();
        }
        // C = 0.5 * max(|a|^2 + |t|^2 - 2 a.t, 0), stride 53
        if (rowAct) {
#pragma unroll
            for (int i = 0; i < 8; ++i) {
                int l = ty * 8 + i;
#pragma unroll
                for (int j = 0; j < 4; ++j) {
                    int r = tx * 4 + j;
                    if (r < R_) Cs[l * 53 + r] = 0.5f * fmaxf(na[l] + nt[r] - 2.f * acc[i][j], 0.f);
                }
            }
        }
        __syncthreads();

        sinkhorn_run<L_, R_, 53, 4, 2, 8>(Cs, lw, sm + AB_F, sm + AB_G,
                                          sm + AB_FA, sm + AB_GB, tid, NA);

        // OT value = sum_n w_n f_n + (1/R) sum_m g_m
        float part = 0.f;
        const float* f = sm + AB_F;
        const float* g = sm + AB_G;
        for (int n = tid; n < NA; n += 256) part = fmaf(wv[n], f[n], part);
        for (int m = tid; m < R_; m += 256) part = fmaf(WR_, g[m], part);
        part = wred_sum(part);
        if (lane == 0) sm[AB_RED + warp] = part;
        __syncthreads();
        if (tid == 0) {
            float s = 0.f;
#pragma unroll
            for (int w = 0; w < 8; ++w) s += sm[AB_RED + w];
            g_ab[id] = s;
        }
    } else {
        // ================= tt path: one CTA per (i,j) =================
        const int id = blockIdx.x - NAB;
        const int i0 = id / K_;
        const int j0 = id - i0 * K_;
        const float* TA = t0 + i0 * (R_ * D_);
        const float* TB = t0 + j0 * (R_ * D_);

        float* As = sm + TT_AS;
        float* Bs = sm + TT_BS;
        float* Cs = sm + TT_CS;
        float* na = sm + TT_NA;
        float* nb = sm + TT_NB;
        float* la = sm + TT_LA;

        if (tid < 64) la[tid] = LOGR;
        for (int row = warp; row < R_; row += 8) {
            float s = 0.f;
            for (int d = lane; d < D_; d += 32) { float x = TA[row * D_ + d]; s = fmaf(x, x, s); }
            s = wred_sum(s);
            if (lane == 0) na[row] = s;
        }
        for (int row = warp; row < R_; row += 8) {
            float s = 0.f;
            for (int d = lane; d < D_; d += 32) { float x = TB[row * D_ + d]; s = fmaf(x, x, s); }
            s = wred_sum(s);
            if (lane == 0) nb[row] = s;
        }
        __syncthreads();

        // GEMM 50x50x300 (padded 64x64), 4x4 register tile, stage stride 17
        float acc[4][4];
#pragma unroll
        for (int i = 0; i < 4; ++i)
#pragma unroll
            for (int j = 0; j < 4; ++j) acc[i][j] = 0.f;

        for (int d0 = 0; d0 < D_; d0 += 16) {
            const int rem = D_ - d0;
            for (int idx = tid; idx < 64 * 16; idx += 256) {
                int r = idx >> 4, kk = idx & 15;
                As[r * 17 + kk] = (r < R_ && kk < rem) ? TA[r * D_ + d0 + kk] : 0.f;
                Bs[r * 17 + kk] = (r < R_ && kk < rem) ? TB[r * D_ + d0 + kk] : 0.f;
            }
            __syncthreads();
#pragma unroll
            for (int kk = 0; kk < 16; ++kk) {
                float av[4], bv[4];
#pragma unroll
                for (int i = 0; i < 4; ++i) av[i] = As[(ty * 4 + i) * 17 + kk];
#pragma unroll
                for (int j = 0; j < 4; ++j) bv[j] = Bs[(tx * 4 + j) * 17 + kk];
#pragma unroll
                for (int i = 0; i < 4; ++i)
#pragma unroll
                    for (int j = 0; j < 4; ++j) acc[i][j] = fmaf(av[i], bv[j], acc[i][j]);
            }
            __syncthreads();
        }
#pragma unroll
        for (int i = 0; i < 4; ++i) {
            int r0 = ty * 4 + i;
#pragma unroll
            for (int j = 0; j < 4; ++j) {
                int r1 = tx * 4 + j;
                if (r0 < R_ && r1 < R_)
                    Cs[r0 * 51 + r1] = 0.5f * fmaxf(na[r0] + nb[r1] - 2.f * acc[i][j], 0.f);
            }
        }
        __syncthreads();

        sinkhorn_run<R_, R_, 51, 2, 2, 8>(Cs, la, sm + TT_F, sm + TT_G,
                                          sm + TT_FA, sm + TT_GB, tid, R_);

        float part = 0.f;
        const float* f = sm + TT_F;
        const float* g = sm + TT_G;
        for (int n = tid; n < R_; n += 256) part = fmaf(WR_, f[n], part);
        for (int m = tid; m < R_; m += 256) part = fmaf(WR_, g[m], part);
        part = wred_sum(part);
        if (lane == 0) sm[TT_RED + warp] = part;
        __syncthreads();
        if (tid == 0) {
            float s = 0.f;
#pragma unroll
            for (int w = 0; w < 8; ++w) s += sm[TT_RED + w];
            g_tt[id] = s;
        }
    }
}

// ---------------------------------------------------------------------------
// Finisher: hinge loss over (b,k), prototype regularizer, single scalar out.
// ot_aa cancels in pos - d, so d~[b,k] = ot_ab[b,k] - 0.5*self_t[k] suffices.
// ---------------------------------------------------------------------------
__global__ void __launch_bounds__(128)
fin_kernel(const int* __restrict__ grade, float* __restrict__ out)
{
    __shared__ float st[K_];
    __shared__ float red2[4];
    const int tid = threadIdx.x;
    if (tid < K_) st[tid] = g_tt[tid * K_ + tid];
    __syncthreads();

    const int b = tid;   // 128 threads == B_
    float dt[K_];
#pragma unroll
    for (int k = 0; k < K_; ++k) dt[k] = g_ab[b * K_ + k] - 0.5f * st[k];
    const int gr = grade[b];
    float pos = 0.f;
#pragma unroll
    for (int k = 0; k < K_; ++k) if (k == gr) pos = dt[k];
    float l = -MARGIN;
#pragma unroll
    for (int k = 0; k < K_; ++k) l += fmaxf(pos - dt[k] + MARGIN, 0.f);

    l = wred_sum(l);
    if ((tid & 31) == 0) red2[tid >> 5] = l;
    __syncthreads();
    if (tid == 0) {
        float s = red2[0] + red2[1] + red2[2] + red2[3];
        float mean = s * (1.0f / (float)B_);
        float dis = 0.f;
        for (int i = 0; i < K_ * K_; ++i) dis += g_tt[i];
        float sd = 0.f;
        for (int k = 0; k < K_; ++k) sd += st[k];
        dis -= (float)K_ * sd;
        out[0] = mean - dis * 0.01f;
    }
}

extern "C" void kernel_launch(void* const* d_in, const int* in_sizes, int n_in,
                              void* d_out, int out_size)
{
    const float* anchor = (const float*)d_in[0];
    const float* weight = (const float*)d_in[1];
    const float* t0     = (const float*)d_in[2];
    const int*   len    = (const int*)d_in[3];
    const int*   grade  = (const int*)d_in[4];

    ot_kernel<<<NAB + 100, 256>>>(anchor, weight, t0, len);
    fin_kernel<<<1, 128>>>(grade, (float*)d_out);
}

// round 6
// speedup vs baseline: 1.6028x; 1.6028x over previous
#include <cuda_runtime.h>
#include <cuda_bf16.h>

#define B_ 128
#define L_ 128
#define D_ 300
#define K_ 10
#define R_ 50
#define NAB (B_ * K_)   // 1280 ab problems

namespace {
constexpr int   NITER  = 20;
constexpr float EPS_   = 0.0025f;                  // 0.05^2
constexpr float IEPS   = 400.0f;                   // 1/EPS
constexpr float LOGR   = -3.9120230674743652f;     // -log(50)
constexpr float WR_    = 0.02f;                    // 1/50
constexpr float NEGV   = -1e9f;
constexpr float MARGIN = 10.0f;
constexpr float FLOOR_ = -3.0e38f;
}

// scratch (no allocations allowed)
__device__ float g_ab[NAB];
__device__ float g_tt[K_ * K_];

__device__ __forceinline__ float wred_sum(float v) {
#pragma unroll
    for (int o = 16; o > 0; o >>= 1) v += __shfl_xor_sync(0xffffffffu, v, o);
    return v;
}

// ---------------------------------------------------------------------------
// Thread-serial log-domain Sinkhorn. M = 50 columns always. Cost matrix in
// smem, row-major, stride CS (odd => conflict-free for both phases):
//   f-phase: one thread per row (lane stride CS, gcd(CS,32)=1), serial over m.
//   g-phase: one thread per column (lane stride 1), serial over n.
// Two-pass LSE (exact max, then exp-sum) with dual accumulators for ILP.
// No warp shuffles anywhere; inactive warps wait at the barrier.
// ---------------------------------------------------------------------------
template<int CS>
__device__ __forceinline__ void sinkhorn_thread(
    const float* __restrict__ Cs, const float* __restrict__ loga,
    float* __restrict__ f, float* __restrict__ g,
    float* __restrict__ fa, float* __restrict__ gb,
    int tid, int nact)
{
    const int M = R_;   // 50
    for (int i = tid; i < M; i += 256) { g[i] = 0.f; gb[i] = LOGR; }
    __syncthreads();

    for (int it = 0; it < NITER; ++it) {
        // ---- f-phase: f_n = -eps * LSE_m( gb_m - C_nm/eps ), thread = row ----
        if (tid < nact) {
            const float* Cr = Cs + tid * CS;
            float mx0 = FLOOR_, mx1 = FLOOR_;
#pragma unroll
            for (int m = 0; m < M; m += 2) {
                mx0 = fmaxf(mx0, fmaf(Cr[m],     -IEPS, gb[m]));
                mx1 = fmaxf(mx1, fmaf(Cr[m + 1], -IEPS, gb[m + 1]));
            }
            float mx = fmaxf(mx0, mx1);
            float s0 = 0.f, s1 = 0.f;
#pragma unroll
            for (int m = 0; m < M; m += 2) {
                s0 += __expf(fmaf(Cr[m],     -IEPS, gb[m])     - mx);
                s1 += __expf(fmaf(Cr[m + 1], -IEPS, gb[m + 1]) - mx);
            }
            float fv = -EPS_ * (mx + __logf(s0 + s1));
            f[tid]  = fv;
            fa[tid] = fmaf(fv, IEPS, loga[tid]);
        }
        __syncthreads();
        // ---- g-phase: g_m = -eps * LSE_n( fa_n - C_nm/eps ), thread = col ----
        if (tid < M) {
            float mx0 = FLOOR_, mx1 = FLOOR_;
            int n = 0;
            for (; n + 1 < nact; n += 2) {
                mx0 = fmaxf(mx0, fmaf(Cs[n * CS + tid],       -IEPS, fa[n]));
                mx1 = fmaxf(mx1, fmaf(Cs[(n + 1) * CS + tid], -IEPS, fa[n + 1]));
            }
            if (n < nact) mx0 = fmaxf(mx0, fmaf(Cs[n * CS + tid], -IEPS, fa[n]));
            float mx = fmaxf(mx0, mx1);
            float s0 = 0.f, s1 = 0.f;
            for (n = 0; n + 1 < nact; n += 2) {
                s0 += __expf(fmaf(Cs[n * CS + tid],       -IEPS, fa[n])     - mx);
                s1 += __expf(fmaf(Cs[(n + 1) * CS + tid], -IEPS, fa[n + 1]) - mx);
            }
            if (n < nact) s0 += __expf(fmaf(Cs[n * CS + tid], -IEPS, fa[n]) - mx);
            float gv = -EPS_ * (mx + __logf(s0 + s1));
            g[tid]  = gv;
            gb[tid] = fmaf(gv, IEPS, LOGR);
        }
        __syncthreads();
    }
}

// ---------------------------------------------------------------------------
// Fused OT kernel. Blocks [0, 1280): ab problems ((b,k), NA x 50) — launched
// first, they are the long poles. Blocks [1280, 1380): tt problems (50x50).
// ---------------------------------------------------------------------------

// shared-memory carve (floats), ab path:
#define AB_AT   0        // At[16*132] transposed A chunk  (2112)
#define AB_TT   2112     // Tt[16*68]  transposed T chunk  (1088)
#define AB_CS   3200     // Cs[128*53]                     (6784)
#define AB_NA   9984     // na[128]
#define AB_NT   10112    // nt[64]
#define AB_LW   10176    // lw[128]
#define AB_WV   10304    // wv[128]
#define AB_F    10432    // f[128]
#define AB_FA   10560    // fa[128]
#define AB_G    10688    // g[64]
#define AB_GB   10752    // gb[64]
#define AB_RED  10816    // red[8]
#define SM_TOT  10824    // 43296 bytes

// tt path (aliases inside SM_TOT):
#define TT_AS   0        // As[64*17]  (1088)
#define TT_BS   1088     // Bs[64*17]  (1088)
#define TT_CS   2176     // Cs[50*51]  (2550)
#define TT_NA   4726     // na[64]
#define TT_NB   4790     // nb[64]
#define TT_LA   4854     // la[64]
#define TT_F    4918     // f[64]
#define TT_FA   4982     // fa[64]
#define TT_G    5046     // g[64]
#define TT_GB   5110     // gb[64]
#define TT_RED  5174     // red[8]

__global__ void __launch_bounds__(256, 3)
ot_kernel(const float* __restrict__ anchor, const float* __restrict__ weight,
          const float* __restrict__ t0, const int* __restrict__ len)
{
    __shared__ __align__(16) float sm[SM_TOT];
    const int tid  = threadIdx.x;
    const int lane = tid & 31, warp = tid >> 5;
    const int tx = tid & 15, ty = tid >> 4;

    if (blockIdx.x < NAB) {
        // ================= ab path: one CTA per (b,k) =================
        const int id = blockIdx.x;
        const int b  = id / K_;
        const int k  = id - b * K_;
        const float* A = anchor + b * (L_ * D_);
        const float* T = t0 + k * (R_ * D_);
        const int lenb = __ldg(len + b);
        const int NA   = min(L_, (lenb + 7) & ~7);   // active rows, multiple of 8

        float* At = sm + AB_AT;
        float* Tt = sm + AB_TT;
        float* Cs = sm + AB_CS;
        float* na = sm + AB_NA;
        float* nt = sm + AB_NT;
        float* lw = sm + AB_LW;
        float* wv = sm + AB_WV;

        // masked log-weights
        if (tid < L_) {
            float w = weight[b * L_ + tid];
            bool valid = tid < lenb;
            wv[tid] = valid ? w : 0.f;
            lw[tid] = valid ? __logf(fmaxf(w, 1e-12f)) : NEGV;
        }
        // squared norms (only active A rows needed)
        for (int row = warp; row < NA; row += 8) {
            float s = 0.f;
            for (int d = lane; d < D_; d += 32) { float x = A[row * D_ + d]; s = fmaf(x, x, s); }
            s = wred_sum(s);
            if (lane == 0) na[row] = s;
        }
        for (int row = warp; row < R_; row += 8) {
            float s = 0.f;
            for (int d = lane; d < D_; d += 32) { float x = T[row * D_ + d]; s = fmaf(x, x, s); }
            s = wred_sum(s);
            if (lane == 0) nt[row] = s;
        }
        __syncthreads();

        // GEMM: dot[l][r] for l < NA, r < 64 (cols >= 50 ignored).
        // 16x16 threads, 8x4 register tile, k-chunks of 16, transposed stages.
        float acc[8][4];
#pragma unroll
        for (int i = 0; i < 8; ++i)
#pragma unroll
            for (int j = 0; j < 4; ++j) acc[i][j] = 0.f;

        const bool rowAct = (ty * 8) < NA;
        for (int d0 = 0; d0 < D_; d0 += 16) {
            const int rem = D_ - d0;   // >=16 except last chunk (12)
            // stage A^T: At[kk*132 + l]
            for (int idx = tid; idx < NA * 16; idx += 256) {
                int kk = idx & 15, l = idx >> 4;
                At[kk * 132 + l] = (kk < rem) ? A[l * D_ + d0 + kk] : 0.f;
            }
            // stage T^T: Tt[kk*68 + r]
            for (int idx = tid; idx < 64 * 16; idx += 256) {
                int kk = idx & 15, r = idx >> 4;
                Tt[kk * 68 + r] = (r < R_ && kk < rem) ? T[r * D_ + d0 + kk] : 0.f;
            }
            __syncthreads();
            if (rowAct) {
#pragma unroll
                for (int kk = 0; kk < 16; ++kk) {
                    float4 a0 = *(const float4*)(At + kk * 132 + ty * 8);
                    float4 a1 = *(const float4*)(At + kk * 132 + ty * 8 + 4);
                    float4 t4 = *(const float4*)(Tt + kk * 68 + tx * 4);
                    float av[8] = {a0.x, a0.y, a0.z, a0.w, a1.x, a1.y, a1.z, a1.w};
                    float tv[4] = {t4.x, t4.y, t4.z, t4.w};
#pragma unroll
                    for (int i = 0; i < 8; ++i)
#pragma unroll
                        for (int j = 0; j < 4; ++j) acc[i][j] = fmaf(av[i], tv[j], acc[i][j]);
                }
            }
            __syncthreads();
        }
        // C = 0.5 * max(|a|^2 + |t|^2 - 2 a.t, 0), stride 53
        if (rowAct) {
#pragma unroll
            for (int i = 0; i < 8; ++i) {
                int l = ty * 8 + i;
#pragma unroll
                for (int j = 0; j < 4; ++j) {
                    int r = tx * 4 + j;
                    if (r < R_) Cs[l * 53 + r] = 0.5f * fmaxf(na[l] + nt[r] - 2.f * acc[i][j], 0.f);
                }
            }
        }
        __syncthreads();

        sinkhorn_thread<53>(Cs, lw, sm + AB_F, sm + AB_G,
                            sm + AB_FA, sm + AB_GB, tid, NA);

        // OT value = sum_n w_n f_n + (1/R) sum_m g_m
        float part = 0.f;
        const float* f = sm + AB_F;
        const float* g = sm + AB_G;
        for (int n = tid; n < NA; n += 256) part = fmaf(wv[n], f[n], part);
        for (int m = tid; m < R_; m += 256) part = fmaf(WR_, g[m], part);
        part = wred_sum(part);
        if (lane == 0) sm[AB_RED + warp] = part;
        __syncthreads();
        if (tid == 0) {
            float s = 0.f;
#pragma unroll
            for (int w = 0; w < 8; ++w) s += sm[AB_RED + w];
            g_ab[id] = s;
        }
    } else {
        // ================= tt path: one CTA per (i,j) =================
        const int id = blockIdx.x - NAB;
        const int i0 = id / K_;
        const int j0 = id - i0 * K_;
        const float* TA = t0 + i0 * (R_ * D_);
        const float* TB = t0 + j0 * (R_ * D_);

        float* As = sm + TT_AS;
        float* Bs = sm + TT_BS;
        float* Cs = sm + TT_CS;
        float* na = sm + TT_NA;
        float* nb = sm + TT_NB;
        float* la = sm + TT_LA;

        if (tid < 64) la[tid] = LOGR;
        for (int row = warp; row < R_; row += 8) {
            float s = 0.f;
            for (int d = lane; d < D_; d += 32) { float x = TA[row * D_ + d]; s = fmaf(x, x, s); }
            s = wred_sum(s);
            if (lane == 0) na[row] = s;
        }
        for (int row = warp; row < R_; row += 8) {
            float s = 0.f;
            for (int d = lane; d < D_; d += 32) { float x = TB[row * D_ + d]; s = fmaf(x, x, s); }
            s = wred_sum(s);
            if (lane == 0) nb[row] = s;
        }
        __syncthreads();

        // GEMM 50x50x300 (padded 64x64), 4x4 register tile, stage stride 17
        float acc[4][4];
#pragma unroll
        for (int i = 0; i < 4; ++i)
#pragma unroll
            for (int j = 0; j < 4; ++j) acc[i][j] = 0.f;

        for (int d0 = 0; d0 < D_; d0 += 16) {
            const int rem = D_ - d0;
            for (int idx = tid; idx < 64 * 16; idx += 256) {
                int r = idx >> 4, kk = idx & 15;
                As[r * 17 + kk] = (r < R_ && kk < rem) ? TA[r * D_ + d0 + kk] : 0.f;
                Bs[r * 17 + kk] = (r < R_ && kk < rem) ? TB[r * D_ + d0 + kk] : 0.f;
            }
            __syncthreads();
#pragma unroll
            for (int kk = 0; kk < 16; ++kk) {
                float av[4], bv[4];
#pragma unroll
                for (int i = 0; i < 4; ++i) av[i] = As[(ty * 4 + i) * 17 + kk];
#pragma unroll
                for (int j = 0; j < 4; ++j) bv[j] = Bs[(tx * 4 + j) * 17 + kk];
#pragma unroll
                for (int i = 0; i < 4; ++i)
#pragma unroll
                    for (int j = 0; j < 4; ++j) acc[i][j] = fmaf(av[i], bv[j], acc[i][j]);
            }
            __syncthreads();
        }
#pragma unroll
        for (int i = 0; i < 4; ++i) {
            int r0 = ty * 4 + i;
#pragma unroll
            for (int j = 0; j < 4; ++j) {
                int r1 = tx * 4 + j;
                if (r0 < R_ && r1 < R_)
                    Cs[r0 * 51 + r1] = 0.5f * fmaxf(na[r0] + nb[r1] - 2.f * acc[i][j], 0.f);
            }
        }
        __syncthreads();

        sinkhorn_thread<51>(Cs, la, sm + TT_F, sm + TT_G,
                            sm + TT_FA, sm + TT_GB, tid, R_);

        float part = 0.f;
        const float* f = sm + TT_F;
        const float* g = sm + TT_G;
        for (int n = tid; n < R_; n += 256) part = fmaf(WR_, f[n], part);
        for (int m = tid; m < R_; m += 256) part = fmaf(WR_, g[m], part);
        part = wred_sum(part);
        if (lane == 0) sm[TT_RED + warp] = part;
        __syncthreads();
        if (tid == 0) {
            float s = 0.f;
#pragma unroll
            for (int w = 0; w < 8; ++w) s += sm[TT_RED + w];
            g_tt[id] = s;
        }
    }
}

// ---------------------------------------------------------------------------
// Finisher: hinge loss over (b,k), prototype regularizer, single scalar out.
// ot_aa cancels in pos - d, so d~[b,k] = ot_ab[b,k] - 0.5*self_t[k] suffices.
// ---------------------------------------------------------------------------
__global__ void __launch_bounds__(128)
fin_kernel(const int* __restrict__ grade, float* __restrict__ out)
{
    __shared__ float st[K_];
    __shared__ float red2[4];
    const int tid = threadIdx.x;
    if (tid < K_) st[tid] = g_tt[tid * K_ + tid];
    __syncthreads();

    const int b = tid;   // 128 threads == B_
    float dt[K_];
#pragma unroll
    for (int k = 0; k < K_; ++k) dt[k] = g_ab[b * K_ + k] - 0.5f * st[k];
    const int gr = grade[b];
    float pos = 0.f;
#pragma unroll
    for (int k = 0; k < K_; ++k) if (k == gr) pos = dt[k];
    float l = -MARGIN;
#pragma unroll
    for (int k = 0; k < K_; ++k) l += fmaxf(pos - dt[k] + MARGIN, 0.f);

    l = wred_sum(l);
    if ((tid & 31) == 0) red2[tid >> 5] = l;
    __syncthreads();
    if (tid == 0) {
        float s = red2[0] + red2[1] + red2[2] + red2[3];
        float mean = s * (1.0f / (float)B_);
        float dis = 0.f;
        for (int i = 0; i < K_ * K_; ++i) dis += g_tt[i];
        float sd = 0.f;
        for (int k = 0; k < K_; ++k) sd += st[k];
        dis -= (float)K_ * sd;
        out[0] = mean - dis * 0.01f;
    }
}

extern "C" void kernel_launch(void* const* d_in, const int* in_sizes, int n_in,
                              void* d_out, int out_size)
{
    const float* anchor = (const float*)d_in[0];
    const float* weight = (const float*)d_in[1];
    const float* t0     = (const float*)d_in[2];
    const int*   len    = (const int*)d_in[3];
    const int*   grade  = (const int*)d_in[4];

    ot_kernel<<<NAB + 100, 256>>>(anchor, weight, t0, len);
    fin_kernel<<<1, 128>>>(grade, (float*)d_out);
}